// round 1
// baseline (speedup 1.0000x reference)
#include <cuda_runtime.h>
#include <math.h>

#define NP   4096
#define NSEQ 512
#define EE   64
#define GG   128
#define KSPLIT 8

// ---------------- scratch (device globals; no allocation allowed) ----------
__device__ float g_f [NP*EE];     // f_nodes_in
__device__ float g_fr[NP*EE];     // relu(f_nodes_in)
__device__ float g_T1[NP*EE];
__device__ float g_T2[NP*EE];
__device__ float g_part[KSPLIT*NP*EE];
__device__ float g_s1[NP];
__device__ float g_seqc[NSEQ];
__device__ float g_w2g[EE*GG];    // w_gcn2 @ w_graph
__device__ float g_w2t[EE*GG];    // w_gcn2 @ w_gate

// ---------------- f_nodes_in = f @ w_feat + b_feat ------------------------
__global__ void ker_feat(const float* __restrict__ f, const float* __restrict__ w,
                         const float* __restrict__ b) {
    __shared__ float fs[4][20];
    int tid = threadIdx.x;
    int r = tid >> 6, c = tid & 63;
    if (tid < 80) fs[tid / 20][tid % 20] = f[blockIdx.x * 80 + tid];
    __syncthreads();
    int row = blockIdx.x * 4 + r;
    float acc = b[c];
#pragma unroll
    for (int a = 0; a < 20; a++) acc = fmaf(fs[r][a], w[a * 64 + c], acc);
    g_f [row * 64 + c] = acc;
    g_fr[row * 64 + c] = fmaxf(acc, 0.f);
}

// ---------------- seqc[k] = relu(x[k]@w_seq + b_seq) . w_edge[128:144] -----
__global__ void ker_seq(const float* __restrict__ x, const float* __restrict__ ws,
                        const float* __restrict__ bs, const float* __restrict__ we) {
    __shared__ float xv[16][20];
    __shared__ float red[16][16];
    int tid = threadIdx.x;
    for (int i = tid; i < 320; i += 256) xv[i / 20][i % 20] = x[blockIdx.x * 320 + i];
    __syncthreads();
    int kk = tid >> 4, s = tid & 15;
    float e = bs[s];
#pragma unroll
    for (int a = 0; a < 20; a++) e = fmaf(xv[kk][a], ws[a * 16 + s], e);
    red[kk][s] = fmaxf(e, 0.f) * we[128 + s];
    __syncthreads();
    if (s == 0) {
        float t = 0.f;
#pragma unroll
        for (int q = 0; q < 16; q++) t += red[kk][q];
        g_seqc[blockIdx.x * 16 + kk] = t;
    }
}

// ---------------- fused weights: w_gcn2 @ w_graph, w_gcn2 @ w_gate ---------
__global__ void ker_fusew(const float* __restrict__ w2, const float* __restrict__ wg,
                          const float* __restrict__ wt) {
    int o = blockIdx.x * 256 + threadIdx.x;         // 0..16383
    int which = o >> 13;
    int q = o & 8191;
    int e = q >> 7, c = q & 127;
    const float* W = which ? wt : wg;
    float acc = 0.f;
#pragma unroll
    for (int m = 0; m < 64; m++) acc = fmaf(w2[e * 64 + m], W[m * 128 + c], acc);
    if (which) g_w2t[q] = acc; else g_w2g[q] = acc;
}

// ---------------- C_partial = A[4096,4096] @ B[4096,64] (split-K) ----------
__global__ void __launch_bounds__(256) ker_gemm64(const float* __restrict__ A, int bsel) {
    const float* __restrict__ B = (bsel == 0) ? g_fr : ((bsel == 1) ? g_T1 : g_T2);
    __shared__ float As[16][64];   // [k][row]
    __shared__ float Bs[16][64];   // [k][col]
    int tid = threadIdx.x;
    int tx = tid & 15, ty = tid >> 4;
    int row0 = blockIdx.x * 64;
    int k0 = blockIdx.y * 512;
    int lr  = tid >> 2;            // 0..63 (A load row)
    int lkq = (tid & 3) * 4;       // k sub-offset
    int lkk = tid >> 4;            // 0..15 (B load k)
    int lc  = (tid & 15) * 4;      // B load col
    float acc[4][4] = {};
    for (int kt = 0; kt < 512; kt += 16) {
        float4 av = *(const float4*)(&A[(size_t)(row0 + lr) * 4096 + (k0 + kt + lkq)]);
        float4 bv = *(const float4*)(&B[(size_t)(k0 + kt + lkk) * 64 + lc]);
        As[lkq + 0][lr] = av.x; As[lkq + 1][lr] = av.y;
        As[lkq + 2][lr] = av.z; As[lkq + 3][lr] = av.w;
        *(float4*)(&Bs[lkk][lc]) = bv;
        __syncthreads();
#pragma unroll
        for (int kk = 0; kk < 16; kk++) {
            float4 a = *(const float4*)(&As[kk][ty * 4]);
            float4 b = *(const float4*)(&Bs[kk][tx * 4]);
            acc[0][0] = fmaf(a.x, b.x, acc[0][0]); acc[0][1] = fmaf(a.x, b.y, acc[0][1]);
            acc[0][2] = fmaf(a.x, b.z, acc[0][2]); acc[0][3] = fmaf(a.x, b.w, acc[0][3]);
            acc[1][0] = fmaf(a.y, b.x, acc[1][0]); acc[1][1] = fmaf(a.y, b.y, acc[1][1]);
            acc[1][2] = fmaf(a.y, b.z, acc[1][2]); acc[1][3] = fmaf(a.y, b.w, acc[1][3]);
            acc[2][0] = fmaf(a.z, b.x, acc[2][0]); acc[2][1] = fmaf(a.z, b.y, acc[2][1]);
            acc[2][2] = fmaf(a.z, b.z, acc[2][2]); acc[2][3] = fmaf(a.z, b.w, acc[2][3]);
            acc[3][0] = fmaf(a.w, b.x, acc[3][0]); acc[3][1] = fmaf(a.w, b.y, acc[3][1]);
            acc[3][2] = fmaf(a.w, b.z, acc[3][2]); acc[3][3] = fmaf(a.w, b.w, acc[3][3]);
        }
        __syncthreads();
    }
    float* Cp = g_part + (size_t)blockIdx.y * (NP * EE);
#pragma unroll
    for (int i = 0; i < 4; i++) {
        int row = row0 + ty * 4 + i;
        *(float4*)(&Cp[row * 64 + tx * 4]) =
            make_float4(acc[i][0], acc[i][1], acc[i][2], acc[i][3]);
    }
}

__global__ void ker_reduce(int csel) {
    float* C = (csel == 1) ? g_T2 : g_T1;
    int i = blockIdx.x * 256 + threadIdx.x;
    float s = 0.f;
#pragma unroll
    for (int q = 0; q < KSPLIT; q++) s += g_part[(size_t)q * (NP * EE) + i];
    C[i] = s;
}

// ---------------- s1[i] = relu(T3[i] @ w_gcn1) . w_edge[0:64] --------------
__global__ void ker_h1s1(const float* __restrict__ w1, const float* __restrict__ we) {
    __shared__ float t[4][64];
    __shared__ float rv[4][64];
    int tid = threadIdx.x;
    int r = tid >> 6, c = tid & 63;
    int row = blockIdx.x * 4 + r;
    t[r][c] = g_T1[row * 64 + c];
    __syncthreads();
    float h = 0.f;
#pragma unroll
    for (int e = 0; e < 64; e++) h = fmaf(t[r][e], w1[e * 64 + c], h);
    rv[r][c] = fmaxf(h, 0.f) * we[c];
    __syncthreads();
    if (c < 32) {
        float v = rv[r][c] + rv[r][c + 32];
#pragma unroll
        for (int off = 16; off; off >>= 1) v += __shfl_down_sync(0xffffffffu, v, off);
        if (c == 0) g_s1[row] = v;
    }
}

// ---------------- scan ------------------------------------------------------
__device__ __forceinline__ float dcoef(int j, int k) {
    // valid only for 0 <= j <= k
    if (k == 0) return 1.f;
    return (j == 0 || j == k) ? 0.70710678118654752f : 0.57735026918962576f;
}

__global__ void __launch_bounds__(512, 1)
ker_scan(const float* __restrict__ wgcn2, const float* __restrict__ bgraph,
         const float* __restrict__ bgate, const float* __restrict__ wedge,
         const float* __restrict__ bedgep, float* __restrict__ out, int out_size) {
    int tid = threadIdx.x, lane = tid & 31, wrp = tid >> 5;
    float s1v[8];
#pragma unroll
    for (int u = 0; u < 8; u++) s1v[u] = g_s1[tid * 8 + u];
    unsigned mk = 0xFFu;  // 8 candidates per thread

    __shared__ float s_red[16];  __shared__ int s_redi[16];
    __shared__ int   s_idxs[NSEQ];
    __shared__ float s_base[GG], s_hgr[GG], s_hlast[EE];
    __shared__ float s_dF[3][EE];
    __shared__ float s_hg[3][GG], s_gg[3][GG];
    __shared__ float s_cred[6];
    __shared__ float s_c;
    __shared__ int   s_idx;

    if (tid < GG) s_base[tid] = 0.f;
    if (tid == 0) s_c = g_seqc[0];
    float bedge = bedgep[0];
    bool write_scores = (out_size >= NP * NSEQ);
    __syncthreads();

    for (int k = 0; k < NSEQ; k++) {
        float c = s_c;
        // --- scores + local argmax
        float best = -INFINITY; int bi = 0;
        float vals[8];
#pragma unroll
        for (int u = 0; u < 8; u++) {
            float v = ((mk >> u) & 1u) ? (s1v[u] + c) + bedge : bedge;
            vals[u] = v;
            if (v > best) { best = v; bi = tid * 8 + u; }
        }
        if (write_scores) {
            float4* o4 = reinterpret_cast<float4*>(out + (size_t)k * NP + tid * 8);
            o4[0] = make_float4(vals[0], vals[1], vals[2], vals[3]);
            o4[1] = make_float4(vals[4], vals[5], vals[6], vals[7]);
        }
#pragma unroll
        for (int off = 16; off; off >>= 1) {
            float ov = __shfl_down_sync(0xffffffffu, best, off);
            int   oi = __shfl_down_sync(0xffffffffu, bi, off);
            if (ov > best || (ov == best && oi < bi)) { best = ov; bi = oi; }
        }
        if (lane == 0) { s_red[wrp] = best; s_redi[wrp] = bi; }
        __syncthreads();
        if (wrp == 0) {
            float bv = (lane < 16) ? s_red[lane] : -INFINITY;
            int   bii = (lane < 16) ? s_redi[lane] : 0x7fffffff;
#pragma unroll
            for (int off = 8; off; off >>= 1) {
                float ov = __shfl_down_sync(0xffffffffu, bv, off);
                int   oi = __shfl_down_sync(0xffffffffu, bii, off);
                if (ov > bv || (ov == bv && oi < bii)) { bv = ov; bii = oi; }
            }
            if (lane == 0) { s_idx = bii; s_idxs[k] = bii; }
        }
        __syncthreads();
        int idx = s_idx;
        if ((idx >> 3) == tid) mk &= ~(1u << (idx & 7));

        // --- dF rows k-2..k (incremental window)
        if (tid < 192) {
            int rr = tid >> 6, cc = tid & 63;
            int j = k - 2 + rr;
            float v = 0.f;
            if (j >= 0) {
                float g0 = (j - 1 >= 0) ? dcoef(j - 1, k) * g_f[s_idxs[j - 1] * 64 + cc] : 0.f;
                float g1 = dcoef(j, k) * g_f[s_idxs[j] * 64 + cc];
                float g2 = (j + 1 <= k) ? dcoef(j + 1, k) * g_f[s_idxs[j + 1] * 64 + cc] : 0.f;
                v = dcoef(j, k) * (g0 + g1 + g2);
            }
            s_dF[rr][cc] = v;
        }
        __syncthreads();

        // --- matvecs: h_last (row k), hg = dF@w2g + b_graph, gg = dF@w2t + b_gate
#pragma unroll
        for (int rep = 0; rep < 2; rep++) {
            int o = tid + rep * 512;
            if (o < 64) {
                float a = 0.f;
#pragma unroll
                for (int e = 0; e < 64; e++) a = fmaf(s_dF[2][e], wgcn2[e * 64 + o], a);
                s_hlast[o] = a;
            } else if (o < 448) {
                int q = o - 64; int rr = q >> 7, cc = q & 127;
                float a = bgraph[cc];
#pragma unroll
                for (int e = 0; e < 64; e++) a = fmaf(s_dF[rr][e], g_w2g[e * 128 + cc], a);
                s_hg[rr][cc] = a;
            } else if (o < 832) {
                int q = o - 448; int rr = q >> 7, cc = q & 127;
                float a = bgate[cc];
#pragma unroll
                for (int e = 0; e < 64; e++) a = fmaf(s_dF[rr][e], g_w2t[e * 128 + cc], a);
                s_gg[rr][cc] = a;
            }
        }
        __syncthreads();

        // --- h_graph = base + contrib(k-2..k); base absorbs row k-2
        if (tid < GG) {
            float base = s_base[tid];
            float hg = base;
#pragma unroll
            for (int rr = 0; rr < 3; rr++) {
                int j = k - 2 + rr;
                if (j >= 0) {
                    float cb = s_hg[rr][tid] / (1.f + expf(-s_gg[rr][tid]));
                    hg += cb;
                    if (rr == 0) base = base + cb;
                }
            }
            s_base[tid] = base;
            s_hgr[tid] = hg;
        }
        __syncthreads();

        // --- c_{k+1}
        if (k < NSEQ - 1) {
            float t = 0.f;
            if (tid < 64)       t = fmaxf(s_hlast[tid], 0.f) * wedge[64 + tid];
            else if (tid < 192) t = fmaxf(s_hgr[tid - 64], 0.f) * wedge[144 + (tid - 64)];
#pragma unroll
            for (int off = 16; off; off >>= 1) t += __shfl_down_sync(0xffffffffu, t, off);
            if (lane == 0 && wrp < 6) s_cred[wrp] = t;
            __syncthreads();
            if (tid == 0) {
                float cc = g_seqc[k + 1];
#pragma unroll
                for (int w = 0; w < 6; w++) cc += s_cred[w];
                s_c = cc;
            }
            __syncthreads();
        }
    }
    if (out_size >= NP * NSEQ + NSEQ)
        out[(size_t)NP * NSEQ + tid] = (float)s_idxs[tid];
}

// ---------------- launch -----------------------------------------------------
extern "C" void kernel_launch(void* const* d_in, const int* in_sizes, int n_in,
                              void* d_out, int out_size) {
    const float* x      = (const float*)d_in[0];
    const float* f      = (const float*)d_in[1];
    const float* a      = (const float*)d_in[2];
    const float* d      = (const float*)d_in[3];
    const float* wfeat  = (const float*)d_in[4];
    const float* bfeat  = (const float*)d_in[5];
    const float* wg1    = (const float*)d_in[6];
    const float* wg2    = (const float*)d_in[7];
    const float* wgraph = (const float*)d_in[8];
    const float* bgraph = (const float*)d_in[9];
    const float* wgate  = (const float*)d_in[10];
    const float* bgate  = (const float*)d_in[11];
    const float* wedge  = (const float*)d_in[12];
    const float* bedge  = (const float*)d_in[13];
    const float* wseq   = (const float*)d_in[14];
    const float* bseq   = (const float*)d_in[15];
    float* out = (float*)d_out;

    ker_feat <<<NP / 4, 256>>>(f, wfeat, bfeat);
    ker_seq  <<<NSEQ / 16, 256>>>(x, wseq, bseq, wedge);
    ker_fusew<<<64, 256>>>(wg2, wgraph, wgate);

    dim3 gg(NP / 64, KSPLIT);
    ker_gemm64<<<gg, 256>>>(d, 0); ker_reduce<<<NP * EE / 256, 256>>>(0);  // T1 = d @ relu(F)
    ker_gemm64<<<gg, 256>>>(a, 1); ker_reduce<<<NP * EE / 256, 256>>>(1);  // T2 = a @ T1
    ker_gemm64<<<gg, 256>>>(d, 2); ker_reduce<<<NP * EE / 256, 256>>>(2);  // T1 = d @ T2  (= dAd@R)

    ker_h1s1<<<NP / 4, 256>>>(wg1, wedge);
    ker_scan<<<1, 512>>>(wg2, bgraph, bgate, wedge, bedge, out, out_size);
}

// round 2
// speedup vs baseline: 1.8936x; 1.8936x over previous
#include <cuda_runtime.h>
#include <math.h>

#define NP   4096
#define NSEQ 512
#define EE   64
#define GG   128
#define KSPLIT 16

// ---------------- scratch (device globals) ---------------------------------
__device__ float g_f [NP*EE];       // f_nodes_in
__device__ float g_fr[NP*EE];       // relu(f_nodes_in)
__device__ float g_T1[NP*EE];
__device__ float g_T2[NP*EE];
__device__ float g_part[KSPLIT*NP*EE];
__device__ float g_s1[NP];
__device__ float g_seqc[NSEQ];
__device__ float g_w2g[EE*GG];      // w_gcn2 @ w_graph
__device__ float g_w2t[EE*GG];      // w_gcn2 @ w_gate
__device__ float g_Pg[NP*GG];       // g_f @ w2g
__device__ float g_Pt[NP*GG];       // g_f @ w2t
__device__ float g_Ph[NP*EE];       // g_f @ w_gcn2

// ---------------- f32x2 packed helpers -------------------------------------
__device__ __forceinline__ unsigned long long pk2(float lo, float hi) {
    unsigned long long r;
    asm("mov.b64 %0, {%1, %2};" : "=l"(r) : "f"(lo), "f"(hi));
    return r;
}
__device__ __forceinline__ void fma2(unsigned long long& d, unsigned long long a,
                                     unsigned long long b) {
    asm("fma.rn.f32x2 %0, %1, %2, %0;" : "+l"(d) : "l"(a), "l"(b));
}
__device__ __forceinline__ float2 upk(unsigned long long v) {
    float2 f;
    asm("mov.b64 {%0, %1}, %2;" : "=f"(f.x), "=f"(f.y) : "l"(v));
    return f;
}

// ---------------- f_nodes_in = f @ w_feat + b_feat -------------------------
__global__ void ker_feat(const float* __restrict__ f, const float* __restrict__ w,
                         const float* __restrict__ b) {
    __shared__ float fs[4][20];
    int tid = threadIdx.x;
    int r = tid >> 6, c = tid & 63;
    if (tid < 80) fs[tid / 20][tid % 20] = f[blockIdx.x * 80 + tid];
    __syncthreads();
    int row = blockIdx.x * 4 + r;
    float acc = b[c];
#pragma unroll
    for (int a = 0; a < 20; a++) acc = fmaf(fs[r][a], w[a * 64 + c], acc);
    g_f [row * 64 + c] = acc;
    g_fr[row * 64 + c] = fmaxf(acc, 0.f);
}

// ---------------- seqc[k] = relu(x[k]@w_seq + b_seq) . w_edge[128:144] -----
__global__ void ker_seq(const float* __restrict__ x, const float* __restrict__ ws,
                        const float* __restrict__ bs, const float* __restrict__ we) {
    __shared__ float xv[16][20];
    __shared__ float red[16][16];
    int tid = threadIdx.x;
    for (int i = tid; i < 320; i += 256) xv[i / 20][i % 20] = x[blockIdx.x * 320 + i];
    __syncthreads();
    int kk = tid >> 4, s = tid & 15;
    float e = bs[s];
#pragma unroll
    for (int a = 0; a < 20; a++) e = fmaf(xv[kk][a], ws[a * 16 + s], e);
    red[kk][s] = fmaxf(e, 0.f) * we[128 + s];
    __syncthreads();
    if (s == 0) {
        float t = 0.f;
#pragma unroll
        for (int q = 0; q < 16; q++) t += red[kk][q];
        g_seqc[blockIdx.x * 16 + kk] = t;
    }
}

// ---------------- fused weights: w_gcn2 @ w_graph, w_gcn2 @ w_gate ---------
__global__ void ker_fusew(const float* __restrict__ w2, const float* __restrict__ wg,
                          const float* __restrict__ wt) {
    int o = blockIdx.x * 256 + threadIdx.x;
    int which = o >> 13;
    int q = o & 8191;
    int e = q >> 7, c = q & 127;
    const float* W = which ? wt : wg;
    float acc = 0.f;
#pragma unroll
    for (int m = 0; m < 64; m++) acc = fmaf(w2[e * 64 + m], W[m * 128 + c], acc);
    if (which) g_w2t[q] = acc; else g_w2g[q] = acc;
}

// ---------------- projections: Pg = F@w2g, Pt = F@w2t, Ph = F@wgcn2 --------
__global__ void __launch_bounds__(320) ker_proj(const float* __restrict__ wgcn2) {
    __shared__ float rows[8][64];
    int tid = threadIdx.x;
    int r0 = blockIdx.x * 8;
    for (int i = tid; i < 512; i += 320)
        rows[i >> 6][i & 63] = g_f[(r0 + (i >> 6)) * 64 + (i & 63)];
    __syncthreads();
    const float* W; int c, stride; float* P; int pstride;
    if (tid < 128)      { W = g_w2g; c = tid;       stride = 128; P = g_Pg; pstride = 128; }
    else if (tid < 256) { W = g_w2t; c = tid - 128; stride = 128; P = g_Pt; pstride = 128; }
    else                { W = wgcn2; c = tid - 256; stride = 64;  P = g_Ph; pstride = 64;  }
    float acc[8] = {0,0,0,0,0,0,0,0};
#pragma unroll 8
    for (int e = 0; e < 64; e++) {
        float w = W[e * stride + c];
#pragma unroll
        for (int r = 0; r < 8; r++) acc[r] = fmaf(rows[r][e], w, acc[r]);
    }
#pragma unroll
    for (int r = 0; r < 8; r++) P[(size_t)(r0 + r) * pstride + c] = acc[r];
}

// ---------------- C_partial = A[4096,4096] @ B[4096,64] (split-K, f32x2) ---
__global__ void __launch_bounds__(128) ker_gemm64(const float* __restrict__ A, int bsel) {
    const float* __restrict__ B = (bsel == 0) ? g_fr : ((bsel == 1) ? g_T1 : g_T2);
    __shared__ float As[16][132];   // k-major, padded (132%32=4 bank shift)
    __shared__ float Bs[16][64];
    int tid = threadIdx.x;
    int tx = tid & 7, ty = tid >> 3;          // microtile coords
    int row0 = blockIdx.x * 128;
    int k0 = blockIdx.y * 256;
    int ar = tid >> 2;                        // A-load row base (0..31)
    int ak = (tid & 3) * 4;                   // A-load k offset
    int bk = tid >> 3;                        // B-load k (0..15)
    int bc = (tid & 7) * 8;                   // B-load col

    unsigned long long acc[8][4];
#pragma unroll
    for (int i = 0; i < 8; i++)
#pragma unroll
        for (int j = 0; j < 4; j++) acc[i][j] = 0ull;

    for (int kt = 0; kt < 256; kt += 16) {
        float4 av[4];
#pragma unroll
        for (int q = 0; q < 4; q++)
            av[q] = *(const float4*)&A[(size_t)(row0 + ar + 32 * q) * 4096 + (k0 + kt + ak)];
        float4 bv0 = *(const float4*)&B[(size_t)(k0 + kt + bk) * 64 + bc];
        float4 bv1 = *(const float4*)&B[(size_t)(k0 + kt + bk) * 64 + bc + 4];
        __syncthreads();
#pragma unroll
        for (int q = 0; q < 4; q++) {
            int r = ar + 32 * q;
            As[ak + 0][r] = av[q].x; As[ak + 1][r] = av[q].y;
            As[ak + 2][r] = av[q].z; As[ak + 3][r] = av[q].w;
        }
        *(float4*)&Bs[bk][bc]     = bv0;
        *(float4*)&Bs[bk][bc + 4] = bv1;
        __syncthreads();
#pragma unroll
        for (int kk = 0; kk < 16; kk++) {
            float4 a0 = *(const float4*)&As[kk][ty * 8];
            float4 a1 = *(const float4*)&As[kk][ty * 8 + 4];
            float4 b0 = *(const float4*)&Bs[kk][tx * 8];
            float4 b1 = *(const float4*)&Bs[kk][tx * 8 + 4];
            unsigned long long bp[4];
            bp[0] = pk2(b0.x, b0.y); bp[1] = pk2(b0.z, b0.w);
            bp[2] = pk2(b1.x, b1.y); bp[3] = pk2(b1.z, b1.w);
            float ar8[8] = {a0.x, a0.y, a0.z, a0.w, a1.x, a1.y, a1.z, a1.w};
#pragma unroll
            for (int i = 0; i < 8; i++) {
                unsigned long long ap = pk2(ar8[i], ar8[i]);
#pragma unroll
                for (int j = 0; j < 4; j++) fma2(acc[i][j], ap, bp[j]);
            }
        }
    }
    float* Cp = g_part + (size_t)blockIdx.y * (NP * EE);
#pragma unroll
    for (int i = 0; i < 8; i++) {
        int row = row0 + ty * 8 + i;
        float2 c0 = upk(acc[i][0]), c1 = upk(acc[i][1]);
        float2 c2 = upk(acc[i][2]), c3 = upk(acc[i][3]);
        float* p = &Cp[(size_t)row * 64 + tx * 8];
        *(float4*)p       = make_float4(c0.x, c0.y, c1.x, c1.y);
        *(float4*)(p + 4) = make_float4(c2.x, c2.y, c3.x, c3.y);
    }
}

__global__ void ker_reduce(int csel) {
    float* C = (csel == 1) ? g_T2 : g_T1;
    int i = blockIdx.x * 256 + threadIdx.x;
    float s = 0.f;
#pragma unroll
    for (int q = 0; q < KSPLIT; q++) s += g_part[(size_t)q * (NP * EE) + i];
    C[i] = s;
}

// ---------------- s1[i] = relu(T1[i] @ w_gcn1) . w_edge[0:64] --------------
__global__ void ker_h1s1(const float* __restrict__ w1, const float* __restrict__ we) {
    __shared__ float t[4][64];
    __shared__ float rv[4][64];
    int tid = threadIdx.x;
    int r = tid >> 6, c = tid & 63;
    int row = blockIdx.x * 4 + r;
    t[r][c] = g_T1[row * 64 + c];
    __syncthreads();
    float h = 0.f;
#pragma unroll
    for (int e = 0; e < 64; e++) h = fmaf(t[r][e], w1[e * 64 + c], h);
    rv[r][c] = fmaxf(h, 0.f) * we[c];
    __syncthreads();
    if (c < 32) {
        float v = rv[r][c] + rv[r][c + 32];
#pragma unroll
        for (int off = 16; off; off >>= 1) v += __shfl_down_sync(0xffffffffu, v, off);
        if (c == 0) g_s1[row] = v;
    }
}

// ---------------- scan ------------------------------------------------------
__device__ __forceinline__ float dcoef(int j, int k) {
    if (k == 0) return 1.f;
    return (j == 0 || j == k) ? 0.70710678118654752f : 0.57735026918962576f;
}

__global__ void __launch_bounds__(512, 1)
ker_scan(const float* __restrict__ bgraph, const float* __restrict__ bgate,
         const float* __restrict__ wedge, const float* __restrict__ bedgep,
         float* __restrict__ out, int out_size) {
    int tid = threadIdx.x, lane = tid & 31, wrp = tid >> 5;
    float s1v[8];
#pragma unroll
    for (int u = 0; u < 8; u++) s1v[u] = g_s1[tid * 8 + u];
    unsigned mk = 0xFFu;

    __shared__ float s_red[16];  __shared__ int s_redi[16];
    __shared__ float sG[4][GG], sT[4][GG], sH[4][EE];
    __shared__ float s_cred[6];
    __shared__ float s_seq[NSEQ];
    __shared__ int   s_idxs[NSEQ];

    s_seq[tid] = g_seqc[tid];
    float bedge = bedgep[0];
    float r_bg = 0.f, r_bt = 0.f, r_weg = 0.f, r_weh = 0.f, base = 0.f;
    if (tid < 128) { r_bg = bgraph[tid]; r_bt = bgate[tid]; r_weg = wedge[144 + tid]; }
    else if (tid < 192) { r_weh = wedge[64 + (tid - 128)]; }
    bool write_scores = (out_size >= NP * NSEQ);
    __syncthreads();
    float c = s_seq[0];

    for (int k = 0; k < NSEQ; k++) {
        // ---- scores + local argmax
        float best = -INFINITY; int bi = 0;
        float vals[8];
#pragma unroll
        for (int u = 0; u < 8; u++) {
            float v = ((mk >> u) & 1u) ? (s1v[u] + c) + bedge : bedge;
            vals[u] = v;
            if (v > best) { best = v; bi = tid * 8 + u; }
        }
        if (write_scores) {
            float4* o4 = reinterpret_cast<float4*>(out + (size_t)k * NP + tid * 8);
            o4[0] = make_float4(vals[0], vals[1], vals[2], vals[3]);
            o4[1] = make_float4(vals[4], vals[5], vals[6], vals[7]);
        }
#pragma unroll
        for (int off = 16; off; off >>= 1) {
            float ov = __shfl_down_sync(0xffffffffu, best, off);
            int   oi = __shfl_down_sync(0xffffffffu, bi, off);
            if (ov > best || (ov == best && oi < bi)) { best = ov; bi = oi; }
        }
        if (lane == 0) { s_red[wrp] = best; s_redi[wrp] = bi; }
        __syncthreads();                                   // barA

        // ---- redundant global argmax (ties -> earliest warp = smaller index)
        float bv = s_red[0]; int idx = s_redi[0];
#pragma unroll
        for (int w = 1; w < 16; w++) {
            float rv = s_red[w];
            if (rv > bv) { bv = rv; idx = s_redi[w]; }
        }
        if (tid == 0) s_idxs[k] = idx;
        if ((idx >> 3) == tid) mk &= ~(1u << (idx & 7));

        // ---- ring load (projected rows of the newly selected node)
        int slot = k & 3;
        if (tid < 128)        sG[slot][tid]       = g_Pg[(size_t)idx * 128 + tid];
        else if (tid < 256)   sT[slot][tid - 128] = g_Pt[(size_t)idx * 128 + (tid - 128)];
        else if (tid < 320)   sH[slot][tid - 256] = g_Ph[(size_t)idx * 64 + (tid - 256)];
        __syncthreads();                                   // barB

        // ---- combos + gating + contributions
        float t = 0.f;
        if (tid < 128) {
            float hgr = base;
#pragma unroll
            for (int rr = 0; rr < 3; rr++) {
                int j = k - 2 + rr;
                if (j < 0) continue;
                float dj = dcoef(j, k);
                float cs = dj * dj;
                float hg = fmaf(cs, sG[j & 3][tid], r_bg);
                float gg = fmaf(cs, sT[j & 3][tid], r_bt);
                if (j >= 1) {
                    float cp = dj * dcoef(j - 1, k);
                    hg = fmaf(cp, sG[(j - 1) & 3][tid], hg);
                    gg = fmaf(cp, sT[(j - 1) & 3][tid], gg);
                }
                if (j + 1 <= k) {
                    float cn = dj * dcoef(j + 1, k);
                    hg = fmaf(cn, sG[(j + 1) & 3][tid], hg);
                    gg = fmaf(cn, sT[(j + 1) & 3][tid], gg);
                }
                float contrib = hg / (1.f + expf(-gg));
                hgr += contrib;
                if (rr == 0) base += contrib;
            }
            t = fmaxf(hgr, 0.f) * r_weg;
        } else if (tid < 192) {
            int o = tid - 128;
            float hl;
            if (k >= 1) {
                float dk = dcoef(k, k);
                hl = dk * fmaf(dcoef(k - 1, k), sH[(k - 1) & 3][o], dk * sH[k & 3][o]);
            } else {
                hl = sH[0][o];
            }
            t = fmaxf(hl, 0.f) * r_weh;
        }
#pragma unroll
        for (int off = 16; off; off >>= 1) t += __shfl_down_sync(0xffffffffu, t, off);
        if (lane == 0 && wrp < 6) s_cred[wrp] = t;
        __syncthreads();                                   // barC

        if (k < NSEQ - 1)
            c = s_seq[k + 1] + ((s_cred[0] + s_cred[1]) + (s_cred[2] + s_cred[3]))
                             + (s_cred[4] + s_cred[5]);
    }
    if (out_size >= NP * NSEQ + NSEQ)
        out[(size_t)NP * NSEQ + tid] = (float)s_idxs[tid];
}

// ---------------- launch -----------------------------------------------------
extern "C" void kernel_launch(void* const* d_in, const int* in_sizes, int n_in,
                              void* d_out, int out_size) {
    const float* x      = (const float*)d_in[0];
    const float* f      = (const float*)d_in[1];
    const float* a      = (const float*)d_in[2];
    const float* d      = (const float*)d_in[3];
    const float* wfeat  = (const float*)d_in[4];
    const float* bfeat  = (const float*)d_in[5];
    const float* wg1    = (const float*)d_in[6];
    const float* wg2    = (const float*)d_in[7];
    const float* wgraph = (const float*)d_in[8];
    const float* bgraph = (const float*)d_in[9];
    const float* wgate  = (const float*)d_in[10];
    const float* bgate  = (const float*)d_in[11];
    const float* wedge  = (const float*)d_in[12];
    const float* bedge  = (const float*)d_in[13];
    const float* wseq   = (const float*)d_in[14];
    const float* bseq   = (const float*)d_in[15];
    float* out = (float*)d_out;

    ker_feat <<<NP / 4, 256>>>(f, wfeat, bfeat);
    ker_seq  <<<NSEQ / 16, 256>>>(x, wseq, bseq, wedge);
    ker_fusew<<<64, 256>>>(wg2, wgraph, wgate);
    ker_proj <<<NP / 8, 320>>>(wg2);

    dim3 gg(NP / 128, KSPLIT);
    ker_gemm64<<<gg, 128>>>(d, 0); ker_reduce<<<NP * EE / 256, 256>>>(0);  // T1 = d @ relu(F)
    ker_gemm64<<<gg, 128>>>(a, 1); ker_reduce<<<NP * EE / 256, 256>>>(1);  // T2 = a @ T1
    ker_gemm64<<<gg, 128>>>(d, 2); ker_reduce<<<NP * EE / 256, 256>>>(2);  // T1 = d @ T2

    ker_h1s1<<<NP / 4, 256>>>(wg1, wedge);
    ker_scan<<<1, 512>>>(bgraph, bgate, wedge, bedge, out, out_size);
}

// round 3
// speedup vs baseline: 3.1821x; 1.6805x over previous
#include <cuda_runtime.h>
#include <math.h>

#define NP   4096
#define NSEQ 512
#define EE   64
#define GG   128
#define KSPLIT 16

// ---------------- scratch (device globals) ---------------------------------
__device__ float g_f [NP*EE];       // f_nodes_in
__device__ float g_fr[NP*EE];       // relu(f_nodes_in)
__device__ float g_T1[NP*EE];
__device__ float g_T2[NP*EE];
__device__ float g_part[KSPLIT*NP*EE];
__device__ float g_s1[NP];
__device__ float g_seqc[NSEQ];
__device__ float g_w2g[EE*GG];      // w_gcn2 @ w_graph
__device__ float g_w2t[EE*GG];      // w_gcn2 @ w_gate
__device__ float g_Pg[NP*GG];       // g_f @ w2g
__device__ float g_Pt[NP*GG];       // g_f @ w2t
__device__ float g_Ph[NP*EE];       // g_f @ w_gcn2
__device__ float g_ordv[NSEQ];      // top-512 sorted s1 values (desc)
__device__ int   g_ordi[NSEQ];      // their indices
__device__ int   g_first[NP];       // first selection step per node (INT_MAX if never)
__device__ float g_cvals[NSEQ];     // c_k per step

// ---------------- f32x2 packed helpers -------------------------------------
__device__ __forceinline__ unsigned long long pk2(float lo, float hi) {
    unsigned long long r;
    asm("mov.b64 %0, {%1, %2};" : "=l"(r) : "f"(lo), "f"(hi));
    return r;
}
__device__ __forceinline__ void fma2(unsigned long long& d, unsigned long long a,
                                     unsigned long long b) {
    asm("fma.rn.f32x2 %0, %1, %2, %0;" : "+l"(d) : "l"(a), "l"(b));
}
__device__ __forceinline__ float2 upk(unsigned long long v) {
    float2 f;
    asm("mov.b64 {%0, %1}, %2;" : "=f"(f.x), "=f"(f.y) : "l"(v));
    return f;
}

// ---------------- f_nodes_in = f @ w_feat + b_feat -------------------------
__global__ void ker_feat(const float* __restrict__ f, const float* __restrict__ w,
                         const float* __restrict__ b) {
    __shared__ float fs[4][20];
    int tid = threadIdx.x;
    int r = tid >> 6, c = tid & 63;
    if (tid < 80) fs[tid / 20][tid % 20] = f[blockIdx.x * 80 + tid];
    __syncthreads();
    int row = blockIdx.x * 4 + r;
    float acc = b[c];
#pragma unroll
    for (int a = 0; a < 20; a++) acc = fmaf(fs[r][a], w[a * 64 + c], acc);
    g_f [row * 64 + c] = acc;
    g_fr[row * 64 + c] = fmaxf(acc, 0.f);
}

// ---------------- seqc[k] = relu(x[k]@w_seq + b_seq) . w_edge[128:144] -----
__global__ void ker_seq(const float* __restrict__ x, const float* __restrict__ ws,
                        const float* __restrict__ bs, const float* __restrict__ we) {
    __shared__ float xv[16][20];
    __shared__ float red[16][16];
    int tid = threadIdx.x;
    for (int i = tid; i < 320; i += 256) xv[i / 20][i % 20] = x[blockIdx.x * 320 + i];
    __syncthreads();
    int kk = tid >> 4, s = tid & 15;
    float e = bs[s];
#pragma unroll
    for (int a = 0; a < 20; a++) e = fmaf(xv[kk][a], ws[a * 16 + s], e);
    red[kk][s] = fmaxf(e, 0.f) * we[128 + s];
    __syncthreads();
    if (s == 0) {
        float t = 0.f;
#pragma unroll
        for (int q = 0; q < 16; q++) t += red[kk][q];
        g_seqc[blockIdx.x * 16 + kk] = t;
    }
}

// ---------------- fused weights: w_gcn2 @ w_graph, w_gcn2 @ w_gate ---------
__global__ void ker_fusew(const float* __restrict__ w2, const float* __restrict__ wg,
                          const float* __restrict__ wt) {
    int o = blockIdx.x * 256 + threadIdx.x;
    int which = o >> 13;
    int q = o & 8191;
    int e = q >> 7, c = q & 127;
    const float* W = which ? wt : wg;
    float acc = 0.f;
#pragma unroll
    for (int m = 0; m < 64; m++) acc = fmaf(w2[e * 64 + m], W[m * 128 + c], acc);
    if (which) g_w2t[q] = acc; else g_w2g[q] = acc;
}

// ---------------- projections: Pg = F@w2g, Pt = F@w2t, Ph = F@wgcn2 --------
__global__ void __launch_bounds__(320) ker_proj(const float* __restrict__ wgcn2) {
    __shared__ float rows[8][64];
    int tid = threadIdx.x;
    int r0 = blockIdx.x * 8;
    for (int i = tid; i < 512; i += 320)
        rows[i >> 6][i & 63] = g_f[(r0 + (i >> 6)) * 64 + (i & 63)];
    __syncthreads();
    const float* W; int c, stride; float* P; int pstride;
    if (tid < 128)      { W = g_w2g; c = tid;       stride = 128; P = g_Pg; pstride = 128; }
    else if (tid < 256) { W = g_w2t; c = tid - 128; stride = 128; P = g_Pt; pstride = 128; }
    else                { W = wgcn2; c = tid - 256; stride = 64;  P = g_Ph; pstride = 64;  }
    float acc[8] = {0,0,0,0,0,0,0,0};
#pragma unroll 8
    for (int e = 0; e < 64; e++) {
        float w = W[e * stride + c];
#pragma unroll
        for (int r = 0; r < 8; r++) acc[r] = fmaf(rows[r][e], w, acc[r]);
    }
#pragma unroll
    for (int r = 0; r < 8; r++) P[(size_t)(r0 + r) * pstride + c] = acc[r];
}

// ---------------- C_partial = A[4096,4096] @ B[4096,64] (split-K, f32x2) ---
__global__ void __launch_bounds__(128) ker_gemm64(const float* __restrict__ A, int bsel) {
    const float* __restrict__ B = (bsel == 0) ? g_fr : ((bsel == 1) ? g_T1 : g_T2);
    __shared__ float As[16][132];
    __shared__ float Bs[16][64];
    int tid = threadIdx.x;
    int tx = tid & 7, ty = tid >> 3;
    int row0 = blockIdx.x * 128;
    int k0 = blockIdx.y * 256;
    int ar = tid >> 2;
    int ak = (tid & 3) * 4;
    int bk = tid >> 3;
    int bc = (tid & 7) * 8;

    unsigned long long acc[8][4];
#pragma unroll
    for (int i = 0; i < 8; i++)
#pragma unroll
        for (int j = 0; j < 4; j++) acc[i][j] = 0ull;

    for (int kt = 0; kt < 256; kt += 16) {
        float4 av[4];
#pragma unroll
        for (int q = 0; q < 4; q++)
            av[q] = *(const float4*)&A[(size_t)(row0 + ar + 32 * q) * 4096 + (k0 + kt + ak)];
        float4 bv0 = *(const float4*)&B[(size_t)(k0 + kt + bk) * 64 + bc];
        float4 bv1 = *(const float4*)&B[(size_t)(k0 + kt + bk) * 64 + bc + 4];
        __syncthreads();
#pragma unroll
        for (int q = 0; q < 4; q++) {
            int r = ar + 32 * q;
            As[ak + 0][r] = av[q].x; As[ak + 1][r] = av[q].y;
            As[ak + 2][r] = av[q].z; As[ak + 3][r] = av[q].w;
        }
        *(float4*)&Bs[bk][bc]     = bv0;
        *(float4*)&Bs[bk][bc + 4] = bv1;
        __syncthreads();
#pragma unroll
        for (int kk = 0; kk < 16; kk++) {
            float4 a0 = *(const float4*)&As[kk][ty * 8];
            float4 a1 = *(const float4*)&As[kk][ty * 8 + 4];
            float4 b0 = *(const float4*)&Bs[kk][tx * 8];
            float4 b1 = *(const float4*)&Bs[kk][tx * 8 + 4];
            unsigned long long bp[4];
            bp[0] = pk2(b0.x, b0.y); bp[1] = pk2(b0.z, b0.w);
            bp[2] = pk2(b1.x, b1.y); bp[3] = pk2(b1.z, b1.w);
            float ar8[8] = {a0.x, a0.y, a0.z, a0.w, a1.x, a1.y, a1.z, a1.w};
#pragma unroll
            for (int i = 0; i < 8; i++) {
                unsigned long long ap = pk2(ar8[i], ar8[i]);
#pragma unroll
                for (int j = 0; j < 4; j++) fma2(acc[i][j], ap, bp[j]);
            }
        }
    }
    float* Cp = g_part + (size_t)blockIdx.y * (NP * EE);
#pragma unroll
    for (int i = 0; i < 8; i++) {
        int row = row0 + ty * 8 + i;
        float2 c0 = upk(acc[i][0]), c1 = upk(acc[i][1]);
        float2 c2 = upk(acc[i][2]), c3 = upk(acc[i][3]);
        float* p = &Cp[(size_t)row * 64 + tx * 8];
        *(float4*)p       = make_float4(c0.x, c0.y, c1.x, c1.y);
        *(float4*)(p + 4) = make_float4(c2.x, c2.y, c3.x, c3.y);
    }
}

__global__ void ker_reduce(int csel) {
    float* C = (csel == 1) ? g_T2 : g_T1;
    int i = blockIdx.x * 256 + threadIdx.x;
    float s = 0.f;
#pragma unroll
    for (int q = 0; q < KSPLIT; q++) s += g_part[(size_t)q * (NP * EE) + i];
    C[i] = s;
}

// ---------------- s1[i] = relu(T1[i] @ w_gcn1) . w_edge[0:64] --------------
__global__ void ker_h1s1(const float* __restrict__ w1, const float* __restrict__ we) {
    __shared__ float t[4][64];
    __shared__ float rv[4][64];
    int tid = threadIdx.x;
    int r = tid >> 6, c = tid & 63;
    int row = blockIdx.x * 4 + r;
    t[r][c] = g_T1[row * 64 + c];
    __syncthreads();
    float h = 0.f;
#pragma unroll
    for (int e = 0; e < 64; e++) h = fmaf(t[r][e], w1[e * 64 + c], h);
    rv[r][c] = fmaxf(h, 0.f) * we[c];
    __syncthreads();
    if (c < 32) {
        float v = rv[r][c] + rv[r][c + 32];
#pragma unroll
        for (int off = 16; off; off >>= 1) v += __shfl_down_sync(0xffffffffu, v, off);
        if (c == 0) g_s1[row] = v;
    }
}

// ---------------- bitonic sort of s1 (desc, index asc tiebreak) ------------
__global__ void __launch_bounds__(1024, 1) ker_sort() {
    __shared__ float v[NP];
    __shared__ int   ix[NP];
    int tid = threadIdx.x;
    for (int i = tid; i < NP; i += 1024) {
        v[i] = g_s1[i]; ix[i] = i; g_first[i] = 0x7fffffff;
    }
    __syncthreads();
    for (int size = 2; size <= NP; size <<= 1) {
        for (int stride = size >> 1; stride > 0; stride >>= 1) {
#pragma unroll
            for (int q = 0; q < 2; q++) {
                int t = tid + q * 1024;
                int lo = ((t & ~(stride - 1)) << 1) | (t & (stride - 1));
                int hi = lo + stride;
                bool desc = ((lo & size) == 0);
                float av = v[lo], bv = v[hi];
                int   ai = ix[lo], bi = ix[hi];
                bool before = (av > bv) || (av == bv && ai < bi);
                if (desc ? !before : before) {
                    v[lo] = bv; v[hi] = av; ix[lo] = bi; ix[hi] = ai;
                }
            }
            __syncthreads();
        }
    }
    for (int i = tid; i < NSEQ; i += 1024) { g_ordv[i] = v[i]; g_ordi[i] = ix[i]; }
}

// ---------------- recurrence: idxs, c_k, first-selection map ----------------
__device__ __forceinline__ float dcoef(int j, int k) {
    if (k == 0) return 1.f;
    return (j == 0 || j == k) ? 0.70710678118654752f : 0.57735026918962576f;
}

__global__ void __launch_bounds__(192, 1)
ker_scanB(const float* __restrict__ bgraph, const float* __restrict__ bgate,
          const float* __restrict__ wedge, const float* __restrict__ bedgep,
          float* __restrict__ out, int out_size) {
    int tid = threadIdx.x, lane = tid & 31, wrp = tid >> 5;
    int o64 = tid - 128;
    __shared__ float s_vals[NSEQ];
    __shared__ int   s_ord[NSEQ];
    __shared__ float s_seq[NSEQ];
    __shared__ int   s_sel[NSEQ];
    __shared__ float s_cred[2][8];
    for (int i = tid; i < NSEQ; i += 192) {
        s_vals[i] = g_ordv[i]; s_ord[i] = g_ordi[i]; s_seq[i] = g_seqc[i];
    }
    if (tid < 16) s_cred[tid >> 3][tid & 7] = 0.f;
    float bedge = bedgep[0];
    float r_bg = 0.f, r_bt = 0.f, r_weg = 0.f, r_weh = 0.f, base = 0.f;
    if (tid < 128) { r_bg = bgraph[tid]; r_bt = bgate[tid]; r_weg = wedge[144 + tid]; }
    else           { r_weh = wedge[64 + o64]; }
    __syncthreads();

    // register rings: rows k-3..k of projected data (columns owned per-thread)
    float rgA=0,rgB=0,rgC=0,rgD=0, rtA=0,rtB=0,rtC=0,rtD=0, rhA=0,rhB=0,rhC=0,rhD=0;
    (void)rhA; (void)rgA;
    int p = 0, minsel = 0x7fffffff;
    float sv = s_vals[0]; int so = s_ord[0];
    float pfg = 0.f, pft = 0.f, pfh = 0.f;
    if (tid < 128) { pfg = g_Pg[(size_t)so * 128 + tid]; pft = g_Pt[(size_t)so * 128 + tid]; }
    else           { pfh = g_Ph[(size_t)so * 64 + o64]; }

    for (int k = 0; k < NSEQ; k++) {
        int rb = k & 1, wb = rb ^ 1;
        float c = s_seq[k]
                + ((s_cred[rb][0] + s_cred[rb][1]) + (s_cred[rb][2] + s_cred[rb][3]))
                + (s_cred[rb][4] + s_cred[rb][5]);
        // --- selection (exact same float comparison as full-score argmax)
        float lhs = (sv + c) + bedge;
        bool spec; int idx;
        if (minsel == 0x7fffffff || lhs > bedge) { spec = true;  idx = so; }
        else if (lhs < bedge)                    { spec = false; idx = minsel; }
        else { if (so < minsel) { spec = true; idx = so; } else { spec = false; idx = minsel; } }
        if (tid == 0) { g_cvals[k] = c; s_sel[k] = idx; if (spec) g_first[idx] = k; }

        // --- ring shift; commit row of idx
        rgA = rgB; rgB = rgC; rgC = rgD;
        rtA = rtB; rtB = rtC; rtC = rtD;
        rhA = rhB; rhB = rhC; rhC = rhD;
        if (spec) {
            rgD = pfg; rtD = pft; rhD = pfh;
            if (idx < minsel) minsel = idx;
            p++;
            int pc = (p < 511) ? p : 511;
            sv = s_vals[pc]; so = s_ord[pc];
            if (tid < 128) { pfg = g_Pg[(size_t)so * 128 + tid]; pft = g_Pt[(size_t)so * 128 + tid]; }
            else           { pfh = g_Ph[(size_t)so * 64 + o64]; }
        } else {
            if (tid < 128) { rgD = g_Pg[(size_t)idx * 128 + tid]; rtD = g_Pt[(size_t)idx * 128 + tid]; }
            else           { rhD = g_Ph[(size_t)idx * 64 + o64]; }
        }

        // --- coefficients (constants for k>=4)
        float a1, a2, a3, b1, b2, b3, c1, c2;
        if (k >= 4) {
            a1 = a2 = a3 = 0.33333333333333333f;
            b1 = b2 = 0.33333333333333333f; b3 = 0.40824829046386302f;
            c1 = 0.40824829046386302f;      c2 = 0.5f;
        } else {
            float djA = (k >= 2) ? dcoef(k - 2, k) : 0.f;
            a1 = (k >= 3) ? djA * dcoef(k - 3, k) : 0.f;
            a2 = djA * djA;
            a3 = (k >= 2) ? djA * dcoef(k - 1, k) : 0.f;
            float djB = (k >= 1) ? dcoef(k - 1, k) : 0.f;
            b1 = (k >= 2) ? djB * dcoef(k - 2, k) : 0.f;
            b2 = djB * djB;
            b3 = (k >= 1) ? djB * dcoef(k, k) : 0.f;
            float djC = dcoef(k, k);
            c1 = (k >= 1) ? djC * dcoef(k - 1, k) : 0.f;
            c2 = djC * djC;
        }

        // --- contributions + reduce to scalar for c_{k+1}
        float t = 0.f;
        if (tid < 128) {
            float hgr;
            if (k >= 2) {
                float hg = r_bg + a1 * rgA + a2 * rgB + a3 * rgC;
                float gg = r_bt + a1 * rtA + a2 * rtB + a3 * rtC;
                float cb = hg / (1.f + expf(-gg));
                base += cb;
            }
            hgr = base;
            if (k >= 1) {
                float hg = r_bg + b1 * rgB + b2 * rgC + b3 * rgD;
                float gg = r_bt + b1 * rtB + b2 * rtC + b3 * rtD;
                hgr += hg / (1.f + expf(-gg));
            }
            {
                float hg = r_bg + c1 * rgC + c2 * rgD;
                float gg = r_bt + c1 * rtC + c2 * rtD;
                hgr += hg / (1.f + expf(-gg));
            }
            t = fmaxf(hgr, 0.f) * r_weg;
        } else {
            float hl = c1 * rhC + c2 * rhD;
            t = fmaxf(hl, 0.f) * r_weh;
        }
#pragma unroll
        for (int off = 16; off; off >>= 1) t += __shfl_down_sync(0xffffffffu, t, off);
        if (lane == 0) s_cred[wb][wrp] = t;
        __syncthreads();
    }
    if (out_size >= NP * NSEQ + NSEQ)
        for (int i = tid; i < NSEQ; i += 192)
            out[(size_t)NP * NSEQ + i] = (float)s_sel[i];
}

// ---------------- parallel score-matrix writeback ---------------------------
__global__ void ker_scores(const float* __restrict__ bedgep, float* __restrict__ out) {
    float bedge = bedgep[0];
    int i0 = blockIdx.x * 1024 + threadIdx.x * 4;
    int k0 = blockIdx.y * 8;
    float4 s1 = *(const float4*)&g_s1[i0];
    int4   fs = *(const int4*)&g_first[i0];
#pragma unroll
    for (int kk = 0; kk < 8; kk++) {
        int k = k0 + kk;
        float c = g_cvals[k];
        float4 vv;
        vv.x = (fs.x >= k) ? (s1.x + c) + bedge : bedge;
        vv.y = (fs.y >= k) ? (s1.y + c) + bedge : bedge;
        vv.z = (fs.z >= k) ? (s1.z + c) + bedge : bedge;
        vv.w = (fs.w >= k) ? (s1.w + c) + bedge : bedge;
        *(float4*)&out[(size_t)k * NP + i0] = vv;
    }
}

// ---------------- launch -----------------------------------------------------
extern "C" void kernel_launch(void* const* d_in, const int* in_sizes, int n_in,
                              void* d_out, int out_size) {
    const float* x      = (const float*)d_in[0];
    const float* f      = (const float*)d_in[1];
    const float* a      = (const float*)d_in[2];
    const float* d      = (const float*)d_in[3];
    const float* wfeat  = (const float*)d_in[4];
    const float* bfeat  = (const float*)d_in[5];
    const float* wg1    = (const float*)d_in[6];
    const float* wg2    = (const float*)d_in[7];
    const float* wgraph = (const float*)d_in[8];
    const float* bgraph = (const float*)d_in[9];
    const float* wgate  = (const float*)d_in[10];
    const float* bgate  = (const float*)d_in[11];
    const float* wedge  = (const float*)d_in[12];
    const float* bedge  = (const float*)d_in[13];
    const float* wseq   = (const float*)d_in[14];
    const float* bseq   = (const float*)d_in[15];
    float* out = (float*)d_out;

    ker_feat <<<NP / 4, 256>>>(f, wfeat, bfeat);
    ker_seq  <<<NSEQ / 16, 256>>>(x, wseq, bseq, wedge);
    ker_fusew<<<64, 256>>>(wg2, wgraph, wgate);
    ker_proj <<<NP / 8, 320>>>(wg2);

    dim3 gg(NP / 128, KSPLIT);
    ker_gemm64<<<gg, 128>>>(d, 0); ker_reduce<<<NP * EE / 256, 256>>>(0);  // T1 = d @ relu(F)
    ker_gemm64<<<gg, 128>>>(a, 1); ker_reduce<<<NP * EE / 256, 256>>>(1);  // T2 = a @ T1
    ker_gemm64<<<gg, 128>>>(d, 2); ker_reduce<<<NP * EE / 256, 256>>>(2);  // T1 = d @ T2

    ker_h1s1<<<NP / 4, 256>>>(wg1, wedge);
    ker_sort<<<1, 1024>>>();
    ker_scanB<<<1, 192>>>(bgraph, bgate, wedge, bedge, out, out_size);
    if (out_size >= NP * NSEQ)
        ker_scores<<<dim3(4, 64), 256>>>(bedge, out);
}